// round 2
// baseline (speedup 1.0000x reference)
#include <cuda_runtime.h>

#define NN 16384
#define DEG 20

typedef unsigned long long u64;

// per-node folded query: qt_s[8], qt_v[8][3]
__device__ float g_qt[NN * 32];

static __device__ __forceinline__ u64 pk2(float lo, float hi) {
    u64 r; asm("mov.b64 %0, {%1, %2};" : "=l"(r) : "f"(lo), "f"(hi)); return r;
}
static __device__ __forceinline__ void upk2(u64 v, float& lo, float& hi) {
    asm("mov.b64 {%0, %1}, %2;" : "=f"(lo), "=f"(hi) : "l"(v));
}
static __device__ __forceinline__ u64 f2(u64 a, u64 b, u64 c) {
    u64 d; asm("fma.rn.f32x2 %0, %1, %2, %3;" : "=l"(d) : "l"(a), "l"(b), "l"(c)); return d;
}
// e3nn soft_unit_step
static __device__ __forceinline__ float ss(float x) {
    return x > 0.f ? __expf(__fdividef(-1.f, x)) : 0.f;
}

// ---------------- K0: fold Wq@Wd/sqrt(8) into per-node query ----------------
__global__ void k0_qt(const float* __restrict__ f, const float* __restrict__ Wq_s,
                      const float* __restrict__ Wq_v, const float* __restrict__ Wd_s,
                      const float* __restrict__ Wd_v) {
    __shared__ float As[64], Av[64];
    int t = threadIdx.x;
    if (t < 64) {
        int m = t >> 3, j = t & 7;
        float s = 0.f, v = 0.f;
#pragma unroll
        for (int o = 0; o < 8; o++) {
            s = fmaf(Wq_s[m * 8 + o], Wd_s[o * 8 + j], s);
            v = fmaf(Wq_v[m * 8 + o], Wd_v[o * 8 + j], v);
        }
        As[t] = s * 0.35355339059327373f;  // 1/sqrt(8)
        Av[t] = v * 0.35355339059327373f;
    }
    __syncthreads();
    int n = blockIdx.x * 256 + t;
    float fs[8], fv[24];
#pragma unroll
    for (int m = 0; m < 8; m++) fs[m] = f[n * 32 + m];
#pragma unroll
    for (int m = 0; m < 24; m++) fv[m] = f[n * 32 + 8 + m];
#pragma unroll
    for (int j = 0; j < 8; j++) {
        float s = 0.f;
#pragma unroll
        for (int m = 0; m < 8; m++) s = fmaf(fs[m], As[m * 8 + j], s);
        g_qt[n * 32 + j] = s;
    }
#pragma unroll
    for (int j = 0; j < 8; j++) {
        float v0 = 0.f, v1 = 0.f, v2 = 0.f;
#pragma unroll
        for (int m = 0; m < 8; m++) {
            float a = Av[m * 8 + j];
            v0 = fmaf(fv[m * 3 + 0], a, v0);
            v1 = fmaf(fv[m * 3 + 1], a, v1);
            v2 = fmaf(fv[m * 3 + 2], a, v2);
        }
        g_qt[n * 32 + 8 + j * 3 + 0] = v0;
        g_qt[n * 32 + 8 + j * 3 + 1] = v1;
        g_qt[n * 32 + 8 + j * 3 + 2] = v2;
    }
}

// ---------------- main kernel: 1 warp per node, fully fused ----------------
// smem (floats): Wk2[16384] Wv2[16384] Wk1[640] Wv1[640] then 16 warp-scratch:
//   h 0..288 (padded t-major), gs 288..320, gdot 320..352, gv 352..448,
//   u 448..460, emb 460..500, lncut 500..504, logit 504..524, coef 524..544
#define SM_WK2 0
#define SM_WV2 16384
#define SM_WK1 32768
#define SM_WV1 33408
#define SM_WS  34048
#define WS_STR 576
#define SMEM_FLOATS (SM_WS + 16 * WS_STR)
#define SMEM_BYTES (SMEM_FLOATS * 4)

__global__ __launch_bounds__(512, 1) void se3_main(
    const float* __restrict__ f, const float* __restrict__ pos,
    const float* __restrict__ Wk1, const float* __restrict__ Wk2,
    const float* __restrict__ Wv1, const float* __restrict__ Wv2,
    const int* __restrict__ edge_src, float* __restrict__ out) {
    extern __shared__ float sm[];
    const int tid = threadIdx.x;
    const int wid = tid >> 5, lane = tid & 31;

    // stage weights
    float4* s4 = (float4*)sm;
    for (int i = tid; i < 4096; i += 512) {
        s4[i] = ((const float4*)Wk2)[i];
        s4[4096 + i] = ((const float4*)Wv2)[i];
    }
    for (int i = tid; i < 160; i += 512) {
        s4[8192 + i] = ((const float4*)Wk1)[i];
        s4[8352 + i] = ((const float4*)Wv1)[i];
    }
    __syncthreads();

    const int n = blockIdx.x * 16 + wid;
    float* ws = sm + SM_WS + wid * WS_STR;
    const int g = lane >> 3, j = lane & 7;              // setup roles
    const int p = lane >> 4, ii = (lane >> 1) & 7, jh = lane & 1;  // FC2 roles

    const float px = pos[n * 3 + 0], py = pos[n * 3 + 1], pz = pos[n * 3 + 2];

    // lane's slice of folded query: j-half jh, 4 outputs
    float qts[4], qtv[4][3];
#pragma unroll
    for (int k = 0; k < 4; k++) {
        qts[k] = g_qt[n * 32 + jh * 4 + k];
#pragma unroll
        for (int c = 0; c < 3; c++) qtv[k][c] = g_qt[n * 32 + 8 + (jh * 4 + k) * 3 + c];
    }

    float outs[4] = {0.f, 0.f, 0.f, 0.f};
    float outv[4][3] = {};

#pragma unroll 1
    for (int pass = 0; pass < 2; pass++) {
        const float* W1 = sm + (pass ? SM_WV1 : SM_WK1);
        const float4* W2 = (const float4*)(sm + (pass ? SM_WV2 : SM_WK2));
#pragma unroll 1
        for (int grp = 0; grp < 5; grp++) {
            // ---- per-edge setup (subgroup g handles edge grp*4+g) ----
            {
                int e = n * DEG + grp * 4 + g;
                int src = edge_src[e];
                float dx = pos[src * 3 + 0] - px;
                float dy = pos[src * 3 + 1] - py;
                float dz = pos[src * 3 + 2] - pz;
                float r2 = fmaf(dx, dx, fmaf(dy, dy, dz * dz));
                float ir = rsqrtf(r2);
                float r = r2 * ir;
                float u0 = dx * ir, u1 = dy * ir, u2 = dz * ir;
                float rr = r * (11.0f / 3.5f);
                {
                    float d = rr - (float)(j + 1);
                    ws[460 + g * 10 + j] = 26.66929f * ss(d + 1.f) * ss(1.f - d);
                    if (j < 2) {
                        float d2 = rr - (float)(j + 9);
                        ws[460 + g * 10 + 8 + j] = 26.66929f * ss(d2 + 1.f) * ss(1.f - d2);
                    }
                }
                float gsv = f[src * 32 + j];
                float a0 = f[src * 32 + 8 + 3 * j + 0];
                float a1 = f[src * 32 + 8 + 3 * j + 1];
                float a2 = f[src * 32 + 8 + 3 * j + 2];
                ws[288 + g * 8 + j] = gsv;
                ws[352 + (g * 8 + j) * 3 + 0] = a0;
                ws[352 + (g * 8 + j) * 3 + 1] = a1;
                ws[352 + (g * 8 + j) * 3 + 2] = a2;
                ws[320 + g * 8 + j] = fmaf(a0, u0, fmaf(a1, u1, a2 * u2));
                if (j == 0) {
                    ws[448 + g * 3 + 0] = u0;
                    ws[448 + g * 3 + 1] = u1;
                    ws[448 + g * 3 + 2] = u2;
                    if (pass == 0) {
                        float x = 10.f * (1.f - r * (1.f / 3.5f));
                        ws[500 + g] = (x > 0.f) ? -__fdividef(1.f, x) : -1e30f;  // ln(cutoff)
                    }
                }
            }
            __syncwarp();
            // ---- FC1: h' = silu(emb@W1/sqrt(10)) / 8  (folds FC2 /sqrt(64)) ----
            {
                float em[10];
#pragma unroll
                for (int b = 0; b < 10; b++) em[b] = ws[460 + g * 10 + b];
#pragma unroll
                for (int k = 0; k < 8; k++) {
                    int t = j * 8 + k;
                    float a = 0.f;
#pragma unroll
                    for (int b = 0; b < 10; b++) a = fmaf(em[b], W1[b * 64 + t], a);
                    a *= 0.31622776601683794f;
                    float h = __fdividef(a, 1.f + __expf(-a));
                    ws[t * 4 + j * 4 + g] = h * 0.125f;  // padded t-major: 36j+4k+g
                }
            }
            __syncwarp();
            // ---- FC2: lane owns flat outputs [4*lane..+3] (path p) and
            //           [128+4*lane..+3] (path p+2), f32x2 packed ----
            u64 accA[4][2], accB[4][2];
#pragma unroll
            for (int e4 = 0; e4 < 4; e4++) {
                accA[e4][0] = 0ULL; accA[e4][1] = 0ULL;
                accB[e4][0] = 0ULL; accB[e4][1] = 0ULL;
            }
            {
                const float4* wp = W2 + lane;
                const float4* hp = (const float4*)ws;
#pragma unroll 4
                for (int t = 0; t < 64; t++) {
                    float4 wA = wp[0];
                    float4 wB = wp[32];
                    float4 h4 = hp[(t >> 3) * 9 + (t & 7)];
                    u64 wa0 = pk2(wA.x, wA.y), wa1 = pk2(wA.z, wA.w);
                    u64 wb0 = pk2(wB.x, wB.y), wb1 = pk2(wB.z, wB.w);
                    u64 hh;
                    hh = pk2(h4.x, h4.x);
                    accA[0][0] = f2(wa0, hh, accA[0][0]); accA[0][1] = f2(wa1, hh, accA[0][1]);
                    accB[0][0] = f2(wb0, hh, accB[0][0]); accB[0][1] = f2(wb1, hh, accB[0][1]);
                    hh = pk2(h4.y, h4.y);
                    accA[1][0] = f2(wa0, hh, accA[1][0]); accA[1][1] = f2(wa1, hh, accA[1][1]);
                    accB[1][0] = f2(wb0, hh, accB[1][0]); accB[1][1] = f2(wb1, hh, accB[1][1]);
                    hh = pk2(h4.z, h4.z);
                    accA[2][0] = f2(wa0, hh, accA[2][0]); accA[2][1] = f2(wa1, hh, accA[2][1]);
                    accB[2][0] = f2(wb0, hh, accB[2][0]); accB[2][1] = f2(wb1, hh, accB[2][1]);
                    hh = pk2(h4.w, h4.w);
                    accA[3][0] = f2(wa0, hh, accA[3][0]); accA[3][1] = f2(wa1, hh, accA[3][1]);
                    accB[3][0] = f2(wb0, hh, accB[3][0]); accB[3][1] = f2(wb1, hh, accB[3][1]);
                    wp += 64;
                }
            }
            // ---- contraction ----
            float lg[4];
#pragma unroll
            for (int e4 = 0; e4 < 4; e4++) {
                float vA[4], vB[4];
                upk2(accA[e4][0], vA[0], vA[1]); upk2(accA[e4][1], vA[2], vA[3]);
                upk2(accB[e4][0], vB[0], vB[1]); upk2(accB[e4][1], vB[2], vB[3]);
                float gse = ws[288 + e4 * 8 + ii];
                float gde = ws[320 + e4 * 8 + ii];
                float uu0 = ws[448 + e4 * 3 + 0];
                float uu1 = ws[448 + e4 * 3 + 1];
                float uu2 = ws[448 + e4 * 3 + 2];
                if (pass == 0) {
                    // logit partial: paths (p, p+2)
                    float sA = (p == 0) ? gse : gde;
                    float dA = fmaf(vA[0], qts[0], fmaf(vA[1], qts[1], fmaf(vA[2], qts[2], vA[3] * qts[3])));
                    float part = sA * dA;
                    if (p == 0) {  // path 2: gs_i * (qt_v[j].u)
                        float s = 0.f;
#pragma unroll
                        for (int k = 0; k < 4; k++) {
                            float qdu = fmaf(qtv[k][0], uu0, fmaf(qtv[k][1], uu1, qtv[k][2] * uu2));
                            s = fmaf(qdu, vB[k], s);
                        }
                        part = fmaf(gse, s, part);
                    } else {       // path 3: (gv_i . qt_v[j]) / sqrt(3)
                        float gv0 = ws[352 + (e4 * 8 + ii) * 3 + 0];
                        float gv1 = ws[352 + (e4 * 8 + ii) * 3 + 1];
                        float gv2 = ws[352 + (e4 * 8 + ii) * 3 + 2];
                        float s = 0.f;
#pragma unroll
                        for (int k = 0; k < 4; k++) {
                            float cc = fmaf(qtv[k][0], gv0, fmaf(qtv[k][1], gv1, qtv[k][2] * gv2));
                            s = fmaf(cc, vB[k], s);
                        }
                        part = fmaf(0.5773502691896258f, s, part);
                    }
                    lg[e4] = part;
                } else {
                    // v-side accumulation weighted by coef (includes 0.25 tp norm)
                    float c4 = ws[524 + grp * 4 + e4];
                    float sA = c4 * ((p == 0) ? gse : gde);
#pragma unroll
                    for (int k = 0; k < 4; k++) outs[k] = fmaf(sA, vA[k], outs[k]);
                    if (p == 0) {  // path 2: sqrt(3)*u[c]*gs_i
                        float b0 = c4 * 1.7320508075688772f * gse;
                        float t0 = b0 * uu0, t1 = b0 * uu1, t2 = b0 * uu2;
#pragma unroll
                        for (int k = 0; k < 4; k++) {
                            outv[k][0] = fmaf(t0, vB[k], outv[k][0]);
                            outv[k][1] = fmaf(t1, vB[k], outv[k][1]);
                            outv[k][2] = fmaf(t2, vB[k], outv[k][2]);
                        }
                    } else {       // path 3: gv_i[c]
                        float gv0 = ws[352 + (e4 * 8 + ii) * 3 + 0] * c4;
                        float gv1 = ws[352 + (e4 * 8 + ii) * 3 + 1] * c4;
                        float gv2 = ws[352 + (e4 * 8 + ii) * 3 + 2] * c4;
#pragma unroll
                        for (int k = 0; k < 4; k++) {
                            outv[k][0] = fmaf(gv0, vB[k], outv[k][0]);
                            outv[k][1] = fmaf(gv1, vB[k], outv[k][1]);
                            outv[k][2] = fmaf(gv2, vB[k], outv[k][2]);
                        }
                    }
                }
            }
            if (pass == 0) {
#pragma unroll
                for (int off = 16; off >= 1; off >>= 1)
#pragma unroll
                    for (int e4 = 0; e4 < 4; e4++)
                        lg[e4] += __shfl_xor_sync(0xffffffffu, lg[e4], off);
                if (lane < 4)
                    ws[504 + grp * 4 + lane] =
                        fmaf(0.022097086912079608f, lg[lane], ws[500 + lane]);  // + ln(cutoff)
            }
            __syncwarp();
        }  // grp
        if (pass == 0) {
            // in-warp softmax over 20 edges; coef includes 0.25 tp norm
            float L = (lane < 20) ? ws[504 + lane] : -3.0e38f;
            float M = L;
#pragma unroll
            for (int off = 16; off >= 1; off >>= 1)
                M = fmaxf(M, __shfl_xor_sync(0xffffffffu, M, off));
            float ex = (lane < 20) ? __expf(L - M) : 0.f;
            float z = ex;
#pragma unroll
            for (int off = 16; off >= 1; off >>= 1)
                z += __shfl_xor_sync(0xffffffffu, z, off);
            if (lane < 20)
                ws[524 + lane] = 0.25f * sqrtf(__fdividef(ex, z) + 1e-12f);
            __syncwarp();
        }
    }  // pass

    // reduce within parity class (preserves j-half); offsets 16,8,4,2
#pragma unroll
    for (int off = 16; off >= 2; off >>= 1) {
#pragma unroll
        for (int k = 0; k < 4; k++) {
            outs[k] += __shfl_xor_sync(0xffffffffu, outs[k], off);
#pragma unroll
            for (int c = 0; c < 3; c++)
                outv[k][c] += __shfl_xor_sync(0xffffffffu, outv[k][c], off);
        }
    }
    if (lane < 2) {
        int o0 = lane * 4;
#pragma unroll
        for (int k = 0; k < 4; k++) {
            out[n * 32 + o0 + k] = outs[k];
#pragma unroll
            for (int c = 0; c < 3; c++)
                out[n * 32 + 8 + (o0 + k) * 3 + c] = outv[k][c];
        }
    }
}

extern "C" void kernel_launch(void* const* d_in, const int* in_sizes, int n_in,
                              void* d_out, int out_size) {
    const float* f    = (const float*)d_in[0];
    const float* pos  = (const float*)d_in[1];
    const float* Wq_s = (const float*)d_in[2];
    const float* Wq_v = (const float*)d_in[3];
    const float* Wk1  = (const float*)d_in[4];
    const float* Wk2  = (const float*)d_in[5];
    const float* Wv1  = (const float*)d_in[6];
    const float* Wv2  = (const float*)d_in[7];
    const float* Wd_s = (const float*)d_in[8];
    const float* Wd_v = (const float*)d_in[9];
    const int* esrc   = (const int*)d_in[10];
    float* out = (float*)d_out;

    cudaFuncSetAttribute(se3_main, cudaFuncAttributeMaxDynamicSharedMemorySize, SMEM_BYTES);
    k0_qt<<<64, 256>>>(f, Wq_s, Wq_v, Wd_s, Wd_v);
    se3_main<<<1024, 512, SMEM_BYTES>>>(f, pos, Wk1, Wk2, Wv1, Wv2, esrc, out);
}